// round 1
// baseline (speedup 1.0000x reference)
#include <cuda_runtime.h>
#include <math.h>

#define BATCH 4
#define SEQ   4096
#define DIM   1024
#define HEADS 16
#define DHEAD 64
#define MROWS (BATCH*SEQ)                 // 16384
#define SCALE 0.5946035575013605f         // (sqrt(64))^(-0.25) = 2^(-0.75)

// ---------------- scratch (device globals; no allocation in kernel_launch) ----
__device__ float g_q[(size_t)MROWS * DIM];     // q projection -> softmaxed q
__device__ float g_v[(size_t)MROWS * DIM];     // v projection
__device__ float g_attn[(size_t)MROWS * DIM];  // attn output before O-proj
__device__ float g_ctx[BATCH * HEADS * DHEAD * DHEAD];
__device__ float g_cmax[BATCH * HEADS * DHEAD];
__device__ float g_cinv[BATCH * HEADS * DHEAD];

// ---------------- fp32 tiled GEMM: C = A[MxK] @ B[KxN] + bias, all row-major --
__global__ __launch_bounds__(256, 2)
void gemm_bias(const float* __restrict__ A, const float* __restrict__ Bm,
               const float* __restrict__ bias, float* __restrict__ C,
               int M, int N, int K)
{
    __shared__ float As[8][128];
    __shared__ float Bs[8][128];
    const int tid = threadIdx.x;
    const int bm = blockIdx.y * 128;
    const int bn = blockIdx.x * 128;
    const int ar = tid >> 1, ac = (tid & 1) * 4;    // A: 128 rows x 8 k
    const int br = tid >> 5, bc = (tid & 31) * 4;   // B: 8 k x 128 cols
    const int tm = (tid >> 4) * 8, tn = (tid & 15) * 8;

    float acc[8][8];
#pragma unroll
    for (int i = 0; i < 8; i++)
#pragma unroll
        for (int j = 0; j < 8; j++) acc[i][j] = 0.f;

    const float* Aptr = A + (size_t)(bm + ar) * K + ac;
    const float* Bptr = Bm + (size_t)br * N + bn + bc;

    for (int k0 = 0; k0 < K; k0 += 8) {
        float4 av = *(const float4*)(Aptr + k0);
        float4 bv = *(const float4*)(Bptr + (size_t)k0 * N);
        As[ac + 0][ar] = av.x;
        As[ac + 1][ar] = av.y;
        As[ac + 2][ar] = av.z;
        As[ac + 3][ar] = av.w;
        *(float4*)&Bs[br][bc] = bv;
        __syncthreads();
#pragma unroll
        for (int kk = 0; kk < 8; kk++) {
            float4 a0 = *(const float4*)&As[kk][tm];
            float4 a1 = *(const float4*)&As[kk][tm + 4];
            float4 b0 = *(const float4*)&Bs[kk][tn];
            float4 b1 = *(const float4*)&Bs[kk][tn + 4];
            float a[8] = {a0.x, a0.y, a0.z, a0.w, a1.x, a1.y, a1.z, a1.w};
            float b[8] = {b0.x, b0.y, b0.z, b0.w, b1.x, b1.y, b1.z, b1.w};
#pragma unroll
            for (int i = 0; i < 8; i++)
#pragma unroll
                for (int j = 0; j < 8; j++) acc[i][j] += a[i] * b[j];
        }
        __syncthreads();
    }

    float bb[8];
#pragma unroll
    for (int j = 0; j < 8; j++) bb[j] = bias[bn + tn + j];
#pragma unroll
    for (int i = 0; i < 8; i++) {
        float* crow = C + (size_t)(bm + tm + i) * N + bn + tn;
        float4 o0 = make_float4(acc[i][0] + bb[0], acc[i][1] + bb[1],
                                acc[i][2] + bb[2], acc[i][3] + bb[3]);
        float4 o1 = make_float4(acc[i][4] + bb[4], acc[i][5] + bb[5],
                                acc[i][6] + bb[6], acc[i][7] + bb[7]);
        *(float4*)&crow[0] = o0;
        *(float4*)&crow[4] = o1;
    }
}

// -------- softmax over d_head (64 contiguous floats per (row, head) segment) --
__global__ void softmax_head(float* __restrict__ q)
{
    int seg  = blockIdx.x * 8 + (threadIdx.x >> 5);
    int lane = threadIdx.x & 31;
    float* p = q + (size_t)seg * 64;
    float x0 = p[lane], x1 = p[lane + 32];
    float m = fmaxf(x0, x1);
#pragma unroll
    for (int o = 16; o; o >>= 1) m = fmaxf(m, __shfl_xor_sync(0xffffffffu, m, o));
    float e0 = expf(x0 - m), e1 = expf(x1 - m);
    float s = e0 + e1;
#pragma unroll
    for (int o = 16; o; o >>= 1) s += __shfl_xor_sync(0xffffffffu, s, o);
    float inv = SCALE / s;
    p[lane]      = e0 * inv;
    p[lane + 32] = e1 * inv;
}

// -------- per-(b,h,d) column max & sum(exp) over seq dim ----------------------
__global__ void col_stats()
{
    int bh = blockIdx.x;                       // 0..63
    int d = threadIdx.x & 63, g = threadIdx.x >> 6;  // 8 n-groups of 512
    const float* base = g_q + (size_t)(bh >> 4) * SEQ * DIM + (bh & 15) * DHEAD + d;
    __shared__ float sm[8][64];

    float m = -1e30f;
    for (int n = g * 512; n < g * 512 + 512; n++)
        m = fmaxf(m, base[(size_t)n * DIM]);
    sm[g][d] = m;
    __syncthreads();
    if (g == 0) {
        float mm = sm[0][d];
#pragma unroll
        for (int i = 1; i < 8; i++) mm = fmaxf(mm, sm[i][d]);
        sm[0][d] = mm;
    }
    __syncthreads();
    float cm = sm[0][d];
    __syncthreads();

    float ssum = 0.f;
    for (int n = g * 512; n < g * 512 + 512; n++)
        ssum += expf(base[(size_t)n * DIM] - cm);
    sm[g][d] = ssum;
    __syncthreads();
    if (g == 0) {
        float t = 0.f;
#pragma unroll
        for (int i = 0; i < 8; i++) t += sm[i][d];
        g_cmax[bh * 64 + d] = cm;
        g_cinv[bh * 64 + d] = SCALE / t;
    }
}

__global__ void zero_ctx()
{
    int i = blockIdx.x * blockDim.x + threadIdx.x;
    if (i < BATCH * HEADS * DHEAD * DHEAD) g_ctx[i] = 0.f;
}

// -------- ctx[b,h,d,e] = sum_n k[n,d] * v[n,e], split-K over n + atomics -----
__global__ __launch_bounds__(256)
void ctx_partial()
{
    int bh = blockIdx.y;
    int n0 = blockIdx.x * 128;
    const size_t rowbase = ((size_t)(bh >> 4) * SEQ + n0);
    const float* qb = g_q + rowbase * DIM + (bh & 15) * DHEAD;
    const float* vb = g_v + rowbase * DIM + (bh & 15) * DHEAD;

    __shared__ float ks[16][64];
    __shared__ float vs[16][64];
    __shared__ float scm[64], sci[64];
    int tid = threadIdx.x;
    if (tid < 64) { scm[tid] = g_cmax[bh * 64 + tid]; sci[tid] = g_cinv[bh * 64 + tid]; }

    const int lr = tid >> 4, lc = (tid & 15) * 4;
    const int td = (tid >> 4) * 4, te = (tid & 15) * 4;
    float acc[4][4];
#pragma unroll
    for (int i = 0; i < 4; i++)
#pragma unroll
        for (int j = 0; j < 4; j++) acc[i][j] = 0.f;
    __syncthreads();

    for (int nt = 0; nt < 128; nt += 16) {
        float4 qv = *(const float4*)&qb[(size_t)(nt + lr) * DIM + lc];
        ks[lr][lc + 0] = expf(qv.x - scm[lc + 0]) * sci[lc + 0];
        ks[lr][lc + 1] = expf(qv.y - scm[lc + 1]) * sci[lc + 1];
        ks[lr][lc + 2] = expf(qv.z - scm[lc + 2]) * sci[lc + 2];
        ks[lr][lc + 3] = expf(qv.w - scm[lc + 3]) * sci[lc + 3];
        *(float4*)&vs[lr][lc] = *(const float4*)&vb[(size_t)(nt + lr) * DIM + lc];
        __syncthreads();
#pragma unroll
        for (int nn = 0; nn < 16; nn++) {
            float kr[4] = {ks[nn][td], ks[nn][td + 1], ks[nn][td + 2], ks[nn][td + 3]};
            float4 vv = *(const float4*)&vs[nn][te];
            float vr[4] = {vv.x, vv.y, vv.z, vv.w};
#pragma unroll
            for (int i = 0; i < 4; i++)
#pragma unroll
                for (int j = 0; j < 4; j++) acc[i][j] += kr[i] * vr[j];
        }
        __syncthreads();
    }

    float* cb = g_ctx + (size_t)bh * 64 * 64;
#pragma unroll
    for (int i = 0; i < 4; i++)
#pragma unroll
        for (int j = 0; j < 4; j++)
            atomicAdd(&cb[(td + i) * 64 + te + j], acc[i][j]);
}

// -------- attn[n,e] = sum_d q[n,d] * ctx[d,e] --------------------------------
__global__ __launch_bounds__(256)
void attn_apply()
{
    int bh = blockIdx.y;
    int n0 = blockIdx.x * 128;
    __shared__ float cs[64][64];
    int tid = threadIdx.x;
    const float* cb = g_ctx + (size_t)bh * 4096;
#pragma unroll
    for (int i = 0; i < 4; i++) {
        int idx = i * 1024 + tid * 4;
        *(float4*)&((float*)cs)[idx] = *(const float4*)&cb[idx];
    }
    const size_t rowbase = ((size_t)(bh >> 4) * SEQ + n0);
    const float* qb = g_q + rowbase * DIM + (bh & 15) * DHEAD;
    float* ob       = g_attn + rowbase * DIM + (bh & 15) * DHEAD;

    const int r0 = (tid >> 3) * 4;   // 4 rows
    const int e0 = (tid & 7) * 8;    // 8 cols
    float acc[4][8];
#pragma unroll
    for (int i = 0; i < 4; i++)
#pragma unroll
        for (int j = 0; j < 8; j++) acc[i][j] = 0.f;
    __syncthreads();

    for (int d4 = 0; d4 < 64; d4 += 4) {
        float4 a[4];
#pragma unroll
        for (int i = 0; i < 4; i++)
            a[i] = *(const float4*)&qb[(size_t)(r0 + i) * DIM + d4];
#pragma unroll
        for (int dd = 0; dd < 4; dd++) {
            float4 b0 = *(const float4*)&cs[d4 + dd][e0];
            float4 b1 = *(const float4*)&cs[d4 + dd][e0 + 4];
#pragma unroll
            for (int i = 0; i < 4; i++) {
                float aa = ((const float*)&a[i])[dd];
                acc[i][0] += aa * b0.x; acc[i][1] += aa * b0.y;
                acc[i][2] += aa * b0.z; acc[i][3] += aa * b0.w;
                acc[i][4] += aa * b1.x; acc[i][5] += aa * b1.y;
                acc[i][6] += aa * b1.z; acc[i][7] += aa * b1.w;
            }
        }
    }
#pragma unroll
    for (int i = 0; i < 4; i++) {
        float* orow = ob + (size_t)(r0 + i) * DIM + e0;
        *(float4*)&orow[0] = make_float4(acc[i][0], acc[i][1], acc[i][2], acc[i][3]);
        *(float4*)&orow[4] = make_float4(acc[i][4], acc[i][5], acc[i][6], acc[i][7]);
    }
}

// -----------------------------------------------------------------------------
extern "C" void kernel_launch(void* const* d_in, const int* in_sizes, int n_in,
                              void* d_out, int out_size)
{
    const float* x  = (const float*)d_in[0];
    const float* Wq = (const float*)d_in[1];
    const float* bq = (const float*)d_in[2];
    // d_in[3], d_in[4]: Wk, bk — dead code in reference, skipped
    const float* Wv = (const float*)d_in[5];
    const float* bv = (const float*)d_in[6];
    const float* Wo = (const float*)d_in[7];
    const float* bo = (const float*)d_in[8];
    float* out = (float*)d_out;

    float *qp, *vp, *ap;
    cudaGetSymbolAddress((void**)&qp, g_q);
    cudaGetSymbolAddress((void**)&vp, g_v);
    cudaGetSymbolAddress((void**)&ap, g_attn);

    dim3 gg(DIM / 128, MROWS / 128);
    gemm_bias<<<gg, 256>>>(x, Wq, bq, qp, MROWS, DIM, DIM);
    gemm_bias<<<gg, 256>>>(x, Wv, bv, vp, MROWS, DIM, DIM);
    softmax_head<<<(MROWS * HEADS) / 8, 256>>>(qp);
    col_stats<<<BATCH * HEADS, 512>>>();
    zero_ctx<<<(BATCH * HEADS * DHEAD * DHEAD + 255) / 256, 256>>>();
    ctx_partial<<<dim3(SEQ / 128, BATCH * HEADS), 256>>>();
    attn_apply<<<dim3(SEQ / 128, BATCH * HEADS), 256>>>();
    gemm_bias<<<gg, 256>>>(ap, Wo, bo, out, MROWS, DIM, DIM);
}

// round 3
// speedup vs baseline: 2.1678x; 2.1678x over previous
#include <cuda_runtime.h>
#include <cuda_bf16.h>
#include <math.h>
#include <stdint.h>

#define BATCH 4
#define SEQ   4096
#define DIM   1024
#define HEADS 16
#define DHEAD 64
#define MROWS (BATCH*SEQ)                 // 16384
#define SCALE 0.5946035575013605f         // (sqrt(64))^(-0.25)

// ---------------- scratch ----------------------------------------------------
__device__ float g_q[(size_t)MROWS * DIM];
__device__ float g_v[(size_t)MROWS * DIM];
__device__ float g_attn[(size_t)MROWS * DIM];
__device__ float g_ctx[BATCH * HEADS * DHEAD * DHEAD];
__device__ float g_cmax[BATCH * HEADS * DHEAD];
__device__ float g_cinv[BATCH * HEADS * DHEAD];
__device__ __nv_bfloat16 g_ahi[(size_t)MROWS * DIM];
__device__ __nv_bfloat16 g_alo[(size_t)MROWS * DIM];
__device__ __nv_bfloat16 g_wthi[3u * DIM * DIM];
__device__ __nv_bfloat16 g_wtlo[3u * DIM * DIM];

// ---------------- helpers ----------------------------------------------------
__device__ __forceinline__ uint32_t smem_u32(const void* p) {
    uint32_t a;
    asm("{ .reg .u64 t; cvta.to.shared.u64 t, %1; cvt.u32.u64 %0, t; }"
        : "=r"(a) : "l"(p));
    return a;
}
__device__ __forceinline__ void cp16(uint32_t dst, const void* src) {
    asm volatile("cp.async.cg.shared.global [%0], [%1], 16;" :: "r"(dst), "l"(src));
}
#define SWZ(x) ((x) ^ (((x) >> 3) & 0x70))

__device__ __forceinline__ void ldsm4(uint32_t addr, uint32_t& r0, uint32_t& r1,
                                      uint32_t& r2, uint32_t& r3) {
    asm volatile("ldmatrix.sync.aligned.m8n8.x4.shared.b16 {%0,%1,%2,%3}, [%4];"
                 : "=r"(r0), "=r"(r1), "=r"(r2), "=r"(r3) : "r"(addr));
}
__device__ __forceinline__ void mma16816(float* d, const uint32_t* a,
                                         const uint32_t* b) {
    asm volatile("mma.sync.aligned.m16n8k16.row.col.f32.bf16.bf16.f32 "
                 "{%0,%1,%2,%3}, {%4,%5,%6,%7}, {%8,%9}, {%0,%1,%2,%3};"
                 : "+f"(d[0]), "+f"(d[1]), "+f"(d[2]), "+f"(d[3])
                 : "r"(a[0]), "r"(a[1]), "r"(a[2]), "r"(a[3]),
                   "r"(b[0]), "r"(b[1]));
}

// ---------------- conversion kernels -----------------------------------------
__global__ void split_bf16(const float4* __restrict__ in, uint2* __restrict__ hi,
                           uint2* __restrict__ lo, int n4)
{
    int i = blockIdx.x * blockDim.x + threadIdx.x;
    if (i >= n4) return;
    float4 v = in[i];
    __nv_bfloat16 h0 = __float2bfloat16(v.x), h1 = __float2bfloat16(v.y);
    __nv_bfloat16 h2 = __float2bfloat16(v.z), h3 = __float2bfloat16(v.w);
    __nv_bfloat16 l0 = __float2bfloat16(v.x - __bfloat162float(h0));
    __nv_bfloat16 l1 = __float2bfloat16(v.y - __bfloat162float(h1));
    __nv_bfloat16 l2 = __float2bfloat16(v.z - __bfloat162float(h2));
    __nv_bfloat16 l3 = __float2bfloat16(v.w - __bfloat162float(h3));
    uint32_t a = (uint32_t)__bfloat16_as_ushort(h0) |
                 ((uint32_t)__bfloat16_as_ushort(h1) << 16);
    uint32_t b = (uint32_t)__bfloat16_as_ushort(h2) |
                 ((uint32_t)__bfloat16_as_ushort(h3) << 16);
    hi[i] = make_uint2(a, b);
    a = (uint32_t)__bfloat16_as_ushort(l0) | ((uint32_t)__bfloat16_as_ushort(l1) << 16);
    b = (uint32_t)__bfloat16_as_ushort(l2) | ((uint32_t)__bfloat16_as_ushort(l3) << 16);
    lo[i] = make_uint2(a, b);
}

// W [K,N] row-major fp32  ->  Wt [N,K] bf16 hi/lo
__global__ void transpose_split(const float* __restrict__ W,
                                __nv_bfloat16* __restrict__ th,
                                __nv_bfloat16* __restrict__ tl)
{
    __shared__ float t[32][33];
    int bx = blockIdx.x * 32, by = blockIdx.y * 32;
    int x = threadIdx.x, y0 = threadIdx.y;
#pragma unroll
    for (int j = 0; j < 32; j += 8)
        t[y0 + j][x] = W[(size_t)(by + y0 + j) * DIM + bx + x];
    __syncthreads();
#pragma unroll
    for (int j = 0; j < 32; j += 8) {
        float v = t[x][y0 + j];
        __nv_bfloat16 h = __float2bfloat16(v);
        __nv_bfloat16 l = __float2bfloat16(v - __bfloat162float(h));
        size_t o = (size_t)(bx + y0 + j) * DIM + by + x;
        th[o] = h;
        tl[o] = l;
    }
}

// ---------------- mma.sync GEMM ----------------------------------------------
// C[16384x1024] = A @ Wt^T + bias   (3 error-compensation passes)
// CTA 128x128, K-tile 64, 3-stage cp.async pipeline, 8 warps (4m x 2n),
// warp tile 32x64 via m16n8k16.
#define NITER 48
#define STG_BYTES 32768   // 16KB A + 16KB B per stage

__global__ __launch_bounds__(256, 2)
void gemm_mma(const __nv_bfloat16* __restrict__ Ahi, const __nv_bfloat16* __restrict__ Alo,
              const __nv_bfloat16* __restrict__ Bhi, const __nv_bfloat16* __restrict__ Blo,
              const float* __restrict__ bias, float* __restrict__ C, int do_softmax)
{
    extern __shared__ char smem_raw[];
    const uint32_t sb = (smem_u32(smem_raw) + 127) & ~127u;
    const int tid = threadIdx.x, wid = tid >> 5, lane = tid & 31;
    const int bm = blockIdx.y * 128, bn = blockIdx.x * 128;
    const int wm = (wid >> 1) * 32;        // warp m offset in CTA
    const int wn = (wid & 1) * 64;         // warp n offset in CTA

    const __nv_bfloat16* APS[3] = {Ahi, Ahi, Alo};
    const __nv_bfloat16* BPS[3] = {Bhi, Blo, Bhi};

    // ---- loader: thread -> row tid/2, 4 x 16B chunks ----
    const int lrow = tid >> 1;
    const int lci = (tid & 1) * 4;
    const uint32_t sdstA = SWZ((uint32_t)(lrow * 128 + lci * 16));

    auto load_tile = [&](int it) {
        const int pass = it >> 4, k0 = (it & 15) << 6;
        const __nv_bfloat16* A = APS[pass] + (size_t)(bm + lrow) * DIM + k0 + lci * 8;
        const __nv_bfloat16* B = BPS[pass] + (size_t)(bn + lrow) * DIM + k0 + lci * 8;
        const uint32_t base = sb + (uint32_t)(it % 3) * STG_BYTES;
#pragma unroll
        for (int i = 0; i < 4; i++) cp16(base + (sdstA + i * 16 * 2 - (SWZ(0)) ) + ((SWZ((uint32_t)(lrow*128 + (lci+i)*16))) - sdstA) , A + i * 8);
#pragma unroll
        for (int i = 0; i < 4; i++) cp16(base + 16384 + SWZ((uint32_t)(lrow * 128 + (lci + i) * 16)), B + i * 8);
        asm volatile("cp.async.commit_group;" ::: "memory");
    };
    // NOTE: the A-loop above must use the same simple form as B; rewrite:
    auto load_tileA = [&](int it) { (void)it; };
    (void)load_tileA;

    // clean loader (used below)
    auto load = [&](int it) {
        const int pass = it >> 4, k0 = (it & 15) << 6;
        const __nv_bfloat16* A = APS[pass] + (size_t)(bm + lrow) * DIM + k0 + lci * 8;
        const __nv_bfloat16* B = BPS[pass] + (size_t)(bn + lrow) * DIM + k0 + lci * 8;
        const uint32_t base = sb + (uint32_t)(it % 3) * STG_BYTES;
#pragma unroll
        for (int i = 0; i < 4; i++)
            cp16(base + SWZ((uint32_t)(lrow * 128 + (lci + i) * 16)), A + i * 8);
#pragma unroll
        for (int i = 0; i < 4; i++)
            cp16(base + 16384 + SWZ((uint32_t)(lrow * 128 + (lci + i) * 16)), B + i * 8);
        asm volatile("cp.async.commit_group;" ::: "memory");
    };
    (void)load_tile;

    float acc[2][8][4];
#pragma unroll
    for (int mb = 0; mb < 2; mb++)
#pragma unroll
        for (int nb = 0; nb < 8; nb++)
#pragma unroll
            for (int j = 0; j < 4; j++) acc[mb][nb][j] = 0.f;

    load(0);
    load(1);

    // ldmatrix lane addressing (within-tile byte offsets, swizzled at use)
    const int la_row = lane & 15;          // A row within 16
    const int la_kh = lane >> 4;           // A k-half
    const int lb_n = ((lane >> 4) << 3) + (lane & 7);  // B n within 16
    const int lb_kh = (lane >> 3) & 1;     // B k-half

    for (int it = 0; it < NITER; it++) {
        asm volatile("cp.async.wait_group 1;" ::: "memory");
        __syncthreads();
        if (it + 2 < NITER) load(it + 2);

        const uint32_t abase = sb + (uint32_t)(it % 3) * STG_BYTES;
        const uint32_t bbase = abase + 16384;
#pragma unroll
        for (int kk = 0; kk < 4; kk++) {
            uint32_t af[2][4];
#pragma unroll
            for (int mb = 0; mb < 2; mb++) {
                uint32_t off = (uint32_t)((wm + mb * 16 + la_row) * 128 +
                                          (kk * 16 + la_kh * 8) * 2);
                ldsm4(abase + SWZ(off), af[mb][0], af[mb][1], af[mb][2], af[mb][3]);
            }
            uint32_t bf[8][2];
#pragma unroll
            for (int nb2 = 0; nb2 < 4; nb2++) {
                uint32_t off = (uint32_t)((wn + nb2 * 16 + lb_n) * 128 +
                                          (kk * 16 + lb_kh * 8) * 2);
                uint32_t r0, r1, r2, r3;
                ldsm4(bbase + SWZ(off), r0, r1, r2, r3);
                bf[nb2 * 2][0] = r0;     bf[nb2 * 2][1] = r1;
                bf[nb2 * 2 + 1][0] = r2; bf[nb2 * 2 + 1][1] = r3;
            }
#pragma unroll
            for (int mb = 0; mb < 2; mb++)
#pragma unroll
                for (int nb = 0; nb < 8; nb++)
                    mma16816(acc[mb][nb], af[mb], bf[nb]);
        }
    }

    // ---- epilogue ----
    const int quad = lane >> 2, qt = lane & 3;
    float bia[8][2];
#pragma unroll
    for (int nb = 0; nb < 8; nb++) {
        int col = bn + wn + nb * 8 + qt * 2;
        bia[nb][0] = bias[col];
        bia[nb][1] = bias[col + 1];
    }
#pragma unroll
    for (int mb = 0; mb < 2; mb++) {
#pragma unroll
        for (int h = 0; h < 2; h++) {
            float v[16];
#pragma unroll
            for (int nb = 0; nb < 8; nb++) {
                v[nb * 2]     = acc[mb][nb][h * 2]     + bia[nb][0];
                v[nb * 2 + 1] = acc[mb][nb][h * 2 + 1] + bia[nb][1];
            }
            if (do_softmax) {
                float m = v[0];
#pragma unroll
                for (int j = 1; j < 16; j++) m = fmaxf(m, v[j]);
                m = fmaxf(m, __shfl_xor_sync(0xffffffffu, m, 1));
                m = fmaxf(m, __shfl_xor_sync(0xffffffffu, m, 2));
                float s = 0.f;
#pragma unroll
                for (int j = 0; j < 16; j++) { v[j] = expf(v[j] - m); s += v[j]; }
                s += __shfl_xor_sync(0xffffffffu, s, 1);
                s += __shfl_xor_sync(0xffffffffu, s, 2);
                float inv = SCALE / s;
#pragma unroll
                for (int j = 0; j < 16; j++) v[j] *= inv;
            }
            int row = bm + wm + mb * 16 + h * 8 + quad;
            float* crow = C + (size_t)row * DIM + bn + wn + qt * 2;
#pragma unroll
            for (int nb = 0; nb < 8; nb++)
                *(float2*)&crow[nb * 8] = make_float2(v[nb * 2], v[nb * 2 + 1]);
        }
    }
}

// ---------------- attention middle --------------------------------------------
__global__ void col_stats()
{
    int bh = blockIdx.x;
    int d = threadIdx.x & 63, g = threadIdx.x >> 6;
    const float* base = g_q + (size_t)(bh >> 4) * SEQ * DIM + (bh & 15) * DHEAD + d;
    __shared__ float sm[8][64];

    float m = -1e30f;
    for (int n = g * 512; n < g * 512 + 512; n++)
        m = fmaxf(m, base[(size_t)n * DIM]);
    sm[g][d] = m;
    __syncthreads();
    if (g == 0) {
        float mm = sm[0][d];
#pragma unroll
        for (int i = 1; i < 8; i++) mm = fmaxf(mm, sm[i][d]);
        sm[0][d] = mm;
    }
    __syncthreads();
    float cm = sm[0][d];
    __syncthreads();

    float ssum = 0.f;
    for (int n = g * 512; n < g * 512 + 512; n++)
        ssum += expf(base[(size_t)n * DIM] - cm);
    sm[g][d] = ssum;
    __syncthreads();
    if (g == 0) {
        float t = 0.f;
#pragma unroll
        for (int i = 0; i < 8; i++) t += sm[i][d];
        g_cmax[bh * 64 + d] = cm;
        g_cinv[bh * 64 + d] = SCALE / t;
    }
}

__global__ void zero_ctx()
{
    int i = blockIdx.x * blockDim.x + threadIdx.x;
    if (i < BATCH * HEADS * DHEAD * DHEAD) g_ctx[i] = 0.f;
}

__global__ __launch_bounds__(256)
void ctx_partial()
{
    int bh = blockIdx.y;
    int n0 = blockIdx.x * 128;
    const size_t rowbase = ((size_t)(bh >> 4) * SEQ + n0);
    const float* qb = g_q + rowbase * DIM + (bh & 15) * DHEAD;
    const float* vb = g_v + rowbase * DIM + (bh & 15) * DHEAD;

    __shared__ float ks[16][64];
    __shared__ float vs[16][64];
    __shared__ float scm[64], sci[64];
    int tid = threadIdx.x;
    if (tid < 64) { scm[tid] = g_cmax[bh * 64 + tid]; sci[tid] = g_cinv[bh * 64 + tid]; }

    const int lr = tid >> 4, lc = (tid & 15) * 4;
    const int td = (tid >> 4) * 4, te = (tid & 15) * 4;
    float acc[4][4];
#pragma unroll
    for (int i = 0; i < 4; i++)
#pragma unroll
        for (int j = 0; j < 4; j++) acc[i][j] = 0.f;
    __syncthreads();

    for (int nt = 0; nt < 128; nt += 16) {
        float4 qv = *(const float4*)&qb[(size_t)(nt + lr) * DIM + lc];
        ks[lr][lc + 0] = expf(qv.x - scm[lc + 0]) * sci[lc + 0];
        ks[lr][lc + 1] = expf(qv.y - scm[lc + 1]) * sci[lc + 1];
        ks[lr][lc + 2] = expf(qv.z - scm[lc + 2]) * sci[lc + 2];
        ks[lr][lc + 3] = expf(qv.w - scm[lc + 3]) * sci[lc + 3];
        *(float4*)&vs[lr][lc] = *(const float4*)&vb[(size_t)(nt + lr) * DIM + lc];
        __syncthreads();
#pragma unroll
        for (int nn = 0; nn < 16; nn++) {
            float kr[4] = {ks[nn][td], ks[nn][td + 1], ks[nn][td + 2], ks[nn][td + 3]};
            float4 vv = *(const float4*)&vs[nn][te];
            float vr[4] = {vv.x, vv.y, vv.z, vv.w};
#pragma unroll
            for (int i = 0; i < 4; i++)
#pragma unroll
                for (int j = 0; j < 4; j++) acc[i][j] += kr[i] * vr[j];
        }
        __syncthreads();
    }

    float* cb = g_ctx + (size_t)bh * 64 * 64;
#pragma unroll
    for (int i = 0; i < 4; i++)
#pragma unroll
        for (int j = 0; j < 4; j++)
            atomicAdd(&cb[(td + i) * 64 + te + j], acc[i][j]);
}

__global__ __launch_bounds__(256)
void attn_apply()
{
    int bh = blockIdx.y;
    int n0 = blockIdx.x * 128;
    __shared__ float cs[64][64];
    int tid = threadIdx.x;
    const float* cb = g_ctx + (size_t)bh * 4096;
#pragma unroll
    for (int i = 0; i < 4; i++) {
        int idx = i * 1024 + tid * 4;
        *(float4*)&((float*)cs)[idx] = *(const float4*)&cb[idx];
    }
    const size_t rowbase = ((size_t)(bh >> 4) * SEQ + n0);
    const float* qb = g_q + rowbase * DIM + (bh & 15) * DHEAD;
    float* ob       = g_attn + rowbase * DIM + (bh & 15) * DHEAD;

    const int r0 = (tid >> 3) * 4;
    const int e0 = (tid & 7) * 8;
    float acc[4][8];
#pragma unroll
    for (int i = 0; i < 4; i++)
#pragma unroll
        for (int j = 0; j < 8; j++) acc[i][j] = 0.f;
    __syncthreads();

    for (int d4 = 0; d4 < 64; d4 += 4) {
        float4 a[4];
#pragma unroll
        for (int i = 0; i < 4; i++)
            a[i] = *(const float4*)&qb[(size_t)(r0 + i) * DIM + d4];
#pragma unroll
        for (int dd = 0; dd < 4; dd++) {
            float4 b0 = *(const float4*)&cs[d4 + dd][e0];
            float4 b1 = *(const float4*)&cs[d4 + dd][e0 + 4];
#pragma unroll
            for (int i = 0; i < 4; i++) {
                float aa = ((const float*)&a[i])[dd];
                acc[i][0] += aa * b0.x; acc[i][1] += aa * b0.y;
                acc[i][2] += aa * b0.z; acc[i][3] += aa * b0.w;
                acc[i][4] += aa * b1.x; acc[i][5] += aa * b1.y;
                acc[i][6] += aa * b1.z; acc[i][7] += aa * b1.w;
            }
        }
    }
#pragma unroll
    for (int i = 0; i < 4; i++) {
        float* orow = ob + (size_t)(r0 + i) * DIM + e0;
        *(float4*)&orow[0] = make_float4(acc[i][0], acc[i][1], acc[i][2], acc[i][3]);
        *(float4*)&orow[4] = make_float4(acc[i][4], acc[i][5], acc[i][6], acc[i][7]);
    }
}

// -----------------------------------------------------------------------------
extern "C" void kernel_launch(void* const* d_in, const int* in_sizes, int n_in,
                              void* d_out, int out_size)
{
    const float* x  = (const float*)d_in[0];
    const float* Wq = (const float*)d_in[1];
    const float* bq = (const float*)d_in[2];
    const float* Wv = (const float*)d_in[5];
    const float* bv = (const float*)d_in[6];
    const float* Wo = (const float*)d_in[7];
    const float* bo = (const float*)d_in[8];
    float* out = (float*)d_out;

    float *qp, *vp, *ap;
    __nv_bfloat16 *ahi, *alo, *wthi, *wtlo;
    cudaGetSymbolAddress((void**)&qp, g_q);
    cudaGetSymbolAddress((void**)&vp, g_v);
    cudaGetSymbolAddress((void**)&ap, g_attn);
    cudaGetSymbolAddress((void**)&ahi, g_ahi);
    cudaGetSymbolAddress((void**)&alo, g_alo);
    cudaGetSymbolAddress((void**)&wthi, g_wthi);
    cudaGetSymbolAddress((void**)&wtlo, g_wtlo);

    const int SMEM = 3 * STG_BYTES + 256;   // ~98.5KB
    cudaFuncSetAttribute(gemm_mma, cudaFuncAttributeMaxDynamicSharedMemorySize, SMEM);

    const int n4 = MROWS * DIM / 4;
    dim3 tgrid(DIM / 32, DIM / 32), tblk(32, 8);
    dim3 ggrid(DIM / 128, MROWS / 128);

    split_bf16<<<(n4 + 255) / 256, 256>>>((const float4*)x, (uint2*)ahi, (uint2*)alo, n4);
    transpose_split<<<tgrid, tblk>>>(Wq, wthi, wtlo);
    transpose_split<<<tgrid, tblk>>>(Wv, wthi + (size_t)DIM * DIM, wtlo + (size_t)DIM * DIM);
    transpose_split<<<tgrid, tblk>>>(Wo, wthi + 2 * (size_t)DIM * DIM, wtlo + 2 * (size_t)DIM * DIM);

    gemm_mma<<<ggrid, 256, SMEM>>>(ahi, alo, wthi, wtlo, bq, qp, 1);
    gemm_mma<<<ggrid, 256, SMEM>>>(ahi, alo, wthi + (size_t)DIM * DIM,
                                   wtlo + (size_t)DIM * DIM, bv, vp, 0);
    col_stats<<<BATCH * HEADS, 512>>>();
    zero_ctx<<<(BATCH * HEADS * DHEAD * DHEAD + 255) / 256, 256>>>();
    ctx_partial<<<dim3(SEQ / 128, BATCH * HEADS), 256>>>();
    attn_apply<<<dim3(SEQ / 128, BATCH * HEADS), 256>>>();
    split_bf16<<<(n4 + 255) / 256, 256>>>((const float4*)ap, (uint2*)ahi, (uint2*)alo, n4);
    gemm_mma<<<ggrid, 256, SMEM>>>(ahi, alo, wthi + 2 * (size_t)DIM * DIM,
                                   wtlo + 2 * (size_t)DIM * DIM, bo, out, 0);
}

// round 4
// speedup vs baseline: 2.2163x; 1.0224x over previous
#include <cuda_runtime.h>
#include <cuda_bf16.h>
#include <math.h>
#include <stdint.h>

#define BATCH 4
#define SEQ   4096
#define DIM   1024
#define HEADS 16
#define DHEAD 64
#define MROWS (BATCH*SEQ)                 // 16384
#define SCALE 0.5946035575013605f         // (sqrt(64))^(-0.25)

// ---------------- scratch ----------------------------------------------------
__device__ float g_q[(size_t)MROWS * DIM];
__device__ float g_v[(size_t)MROWS * DIM];
__device__ float g_ctx[BATCH * HEADS * DHEAD * DHEAD];
__device__ float g_cinv[BATCH * HEADS * DHEAD];
__device__ float g_qsum[BATCH * DIM];
__device__ float g_bqv[2 * DIM];
__device__ __nv_bfloat16 g_ahi[(size_t)MROWS * DIM];
__device__ __nv_bfloat16 g_alo[(size_t)MROWS * DIM];
__device__ __nv_bfloat16 g_wthi[3u * DIM * DIM];
__device__ __nv_bfloat16 g_wtlo[3u * DIM * DIM];

// ---------------- helpers ----------------------------------------------------
__device__ __forceinline__ uint32_t smem_u32(const void* p) {
    uint32_t a;
    asm("{ .reg .u64 t; cvta.to.shared.u64 t, %1; cvt.u32.u64 %0, t; }"
        : "=r"(a) : "l"(p));
    return a;
}
__device__ __forceinline__ void cp16(uint32_t dst, const void* src) {
    asm volatile("cp.async.cg.shared.global [%0], [%1], 16;" :: "r"(dst), "l"(src));
}
#define SWZ(x) ((x) ^ (((x) >> 3) & 0x70))

__device__ __forceinline__ void ldsm4(uint32_t addr, uint32_t& r0, uint32_t& r1,
                                      uint32_t& r2, uint32_t& r3) {
    asm volatile("ldmatrix.sync.aligned.m8n8.x4.shared.b16 {%0,%1,%2,%3}, [%4];"
                 : "=r"(r0), "=r"(r1), "=r"(r2), "=r"(r3) : "r"(addr));
}
__device__ __forceinline__ void mma16816(float* d, const uint32_t* a,
                                         const uint32_t* b) {
    asm volatile("mma.sync.aligned.m16n8k16.row.col.f32.bf16.bf16.f32 "
                 "{%0,%1,%2,%3}, {%4,%5,%6,%7}, {%8,%9}, {%0,%1,%2,%3};"
                 : "+f"(d[0]), "+f"(d[1]), "+f"(d[2]), "+f"(d[3])
                 : "r"(a[0]), "r"(a[1]), "r"(a[2]), "r"(a[3]),
                   "r"(b[0]), "r"(b[1]));
}

// ---------------- conversion / setup kernels ---------------------------------
__global__ void split_bf16(const float4* __restrict__ in, uint2* __restrict__ hi,
                           uint2* __restrict__ lo, int n4)
{
    int i = blockIdx.x * blockDim.x + threadIdx.x;
    if (i >= n4) return;
    float4 v = in[i];
    __nv_bfloat16 h0 = __float2bfloat16(v.x), h1 = __float2bfloat16(v.y);
    __nv_bfloat16 h2 = __float2bfloat16(v.z), h3 = __float2bfloat16(v.w);
    __nv_bfloat16 l0 = __float2bfloat16(v.x - __bfloat162float(h0));
    __nv_bfloat16 l1 = __float2bfloat16(v.y - __bfloat162float(h1));
    __nv_bfloat16 l2 = __float2bfloat16(v.z - __bfloat162float(h2));
    __nv_bfloat16 l3 = __float2bfloat16(v.w - __bfloat162float(h3));
    uint32_t a = (uint32_t)__bfloat16_as_ushort(h0) |
                 ((uint32_t)__bfloat16_as_ushort(h1) << 16);
    uint32_t b = (uint32_t)__bfloat16_as_ushort(h2) |
                 ((uint32_t)__bfloat16_as_ushort(h3) << 16);
    hi[i] = make_uint2(a, b);
    a = (uint32_t)__bfloat16_as_ushort(l0) | ((uint32_t)__bfloat16_as_ushort(l1) << 16);
    b = (uint32_t)__bfloat16_as_ushort(l2) | ((uint32_t)__bfloat16_as_ushort(l3) << 16);
    lo[i] = make_uint2(a, b);
}

// W [K,N] row-major fp32 -> Wt [N,K] bf16 hi/lo
__global__ void transpose_split(const float* __restrict__ W,
                                __nv_bfloat16* __restrict__ th,
                                __nv_bfloat16* __restrict__ tl)
{
    __shared__ float t[32][33];
    int bx = blockIdx.x * 32, by = blockIdx.y * 32;
    int x = threadIdx.x, y0 = threadIdx.y;
#pragma unroll
    for (int j = 0; j < 32; j += 8)
        t[y0 + j][x] = W[(size_t)(by + y0 + j) * DIM + bx + x];
    __syncthreads();
#pragma unroll
    for (int j = 0; j < 32; j += 8) {
        float v = t[x][y0 + j];
        __nv_bfloat16 h = __float2bfloat16(v);
        __nv_bfloat16 l = __float2bfloat16(v - __bfloat162float(h));
        size_t o = (size_t)(bx + y0 + j) * DIM + by + x;
        th[o] = h;
        tl[o] = l;
    }
}

__global__ void setup_misc(const float* __restrict__ bq, const float* __restrict__ bv)
{
    int i = blockIdx.x * blockDim.x + threadIdx.x;
    if (i < DIM) g_bqv[i] = bq[i];
    else if (i < 2 * DIM) g_bqv[i] = bv[i - DIM];
    // zero qsum + ctx
    if (i < BATCH * DIM) g_qsum[i] = 0.f;
    if (i < BATCH * HEADS * DHEAD * DHEAD) g_ctx[i] = 0.f;
}

__global__ void compute_cinv()
{
    int i = blockIdx.x * blockDim.x + threadIdx.x;
    if (i < BATCH * DIM) g_cinv[i] = SCALE / g_qsum[i];
}

// ---------------- mma.sync GEMM ----------------------------------------------
// mode 0: fused QV  (Cq=g_q with softmax+qsum for bn<1024, Cv=g_v for bn>=1024)
// mode 1: plain     (Cq = output, bias)
#define NITER 48
#define STG_BYTES 32768   // 16KB A + 16KB B per stage

__global__ __launch_bounds__(256, 2)
void gemm_mma(const __nv_bfloat16* __restrict__ Ahi, const __nv_bfloat16* __restrict__ Alo,
              const __nv_bfloat16* __restrict__ Bhi, const __nv_bfloat16* __restrict__ Blo,
              const float* __restrict__ bias, float* __restrict__ Cq,
              float* __restrict__ Cv, int mode)
{
    extern __shared__ char smem_raw[];
    const uint32_t sb = (smem_u32(smem_raw) + 127) & ~127u;
    float* scr = (float*)smem_raw;              // reused after mainloop
    const int tid = threadIdx.x, wid = tid >> 5, lane = tid & 31;
    const int bm = blockIdx.y * 128, bn = blockIdx.x * 128;
    const int wm = (wid >> 1) * 32;
    const int wn = (wid & 1) * 64;

    const bool isq = (mode == 0) && (bn < 1024);
    float* C = (mode == 0 && bn >= 1024) ? Cv : Cq;
    const int cbn = (mode == 0 && bn >= 1024) ? bn - 1024 : bn;

    const __nv_bfloat16* APS[3] = {Ahi, Ahi, Alo};
    const __nv_bfloat16* BPS[3] = {Bhi, Blo, Bhi};

    const int lrow = tid >> 1;
    const int lci = (tid & 1) * 4;

    auto load = [&](int it) {
        const int pass = it >> 4, k0 = (it & 15) << 6;
        const __nv_bfloat16* A = APS[pass] + (size_t)(bm + lrow) * DIM + k0 + lci * 8;
        const __nv_bfloat16* B = BPS[pass] + (size_t)(bn + lrow) * DIM + k0 + lci * 8;
        const uint32_t base = sb + (uint32_t)(it % 3) * STG_BYTES;
#pragma unroll
        for (int i = 0; i < 4; i++)
            cp16(base + SWZ((uint32_t)(lrow * 128 + (lci + i) * 16)), A + i * 8);
#pragma unroll
        for (int i = 0; i < 4; i++)
            cp16(base + 16384 + SWZ((uint32_t)(lrow * 128 + (lci + i) * 16)), B + i * 8);
        asm volatile("cp.async.commit_group;" ::: "memory");
    };

    float acc[2][8][4];
#pragma unroll
    for (int mb = 0; mb < 2; mb++)
#pragma unroll
        for (int nb = 0; nb < 8; nb++)
#pragma unroll
            for (int j = 0; j < 4; j++) acc[mb][nb][j] = 0.f;

    load(0);
    load(1);

    const int la_row = lane & 15;
    const int la_kh = lane >> 4;
    const int lb_n = ((lane >> 4) << 3) + (lane & 7);
    const int lb_kh = (lane >> 3) & 1;

    for (int it = 0; it < NITER; it++) {
        asm volatile("cp.async.wait_group 1;" ::: "memory");
        __syncthreads();
        if (it + 2 < NITER) load(it + 2);

        const uint32_t abase = sb + (uint32_t)(it % 3) * STG_BYTES;
        const uint32_t bbase = abase + 16384;
#pragma unroll
        for (int kk = 0; kk < 4; kk++) {
            uint32_t af[2][4];
#pragma unroll
            for (int mb = 0; mb < 2; mb++) {
                uint32_t off = (uint32_t)((wm + mb * 16 + la_row) * 128 +
                                          (kk * 16 + la_kh * 8) * 2);
                ldsm4(abase + SWZ(off), af[mb][0], af[mb][1], af[mb][2], af[mb][3]);
            }
            uint32_t bf[8][2];
#pragma unroll
            for (int nb2 = 0; nb2 < 4; nb2++) {
                uint32_t off = (uint32_t)((wn + nb2 * 16 + lb_n) * 128 +
                                          (kk * 16 + lb_kh * 8) * 2);
                uint32_t r0, r1, r2, r3;
                ldsm4(bbase + SWZ(off), r0, r1, r2, r3);
                bf[nb2 * 2][0] = r0;     bf[nb2 * 2][1] = r1;
                bf[nb2 * 2 + 1][0] = r2; bf[nb2 * 2 + 1][1] = r3;
            }
#pragma unroll
            for (int mb = 0; mb < 2; mb++)
#pragma unroll
                for (int nb = 0; nb < 8; nb++)
                    mma16816(acc[mb][nb], af[mb], bf[nb]);
        }
    }

    // ---- epilogue ----
    __syncthreads();
    if (tid < 128) scr[tid] = 0.f;
    __syncthreads();

    const int quad = lane >> 2, qt = lane & 3;
    float bia[8][2];
#pragma unroll
    for (int nb = 0; nb < 8; nb++) {
        int col = bn + wn + nb * 8 + qt * 2;
        bia[nb][0] = bias[col];
        bia[nb][1] = bias[col + 1];
    }
#pragma unroll
    for (int mb = 0; mb < 2; mb++) {
#pragma unroll
        for (int h = 0; h < 2; h++) {
            float v[16];
#pragma unroll
            for (int nb = 0; nb < 8; nb++) {
                v[nb * 2]     = acc[mb][nb][h * 2]     + bia[nb][0];
                v[nb * 2 + 1] = acc[mb][nb][h * 2 + 1] + bia[nb][1];
            }
            if (isq) {
                // softmax over the 64-col head (warp-wide: 16 local + qt via shfl 1,2)
                float m = v[0];
#pragma unroll
                for (int j = 1; j < 16; j++) m = fmaxf(m, v[j]);
                m = fmaxf(m, __shfl_xor_sync(0xffffffffu, m, 1));
                m = fmaxf(m, __shfl_xor_sync(0xffffffffu, m, 2));
                float s = 0.f;
#pragma unroll
                for (int j = 0; j < 16; j++) { v[j] = expf(v[j] - m); s += v[j]; }
                s += __shfl_xor_sync(0xffffffffu, s, 1);
                s += __shfl_xor_sync(0xffffffffu, s, 2);
                float inv = SCALE / s;
#pragma unroll
                for (int j = 0; j < 16; j++) v[j] *= inv;
                // partial column sums of exp(q) for the seq-softmax (no max needed:
                // q in [0, SCALE], exp bounded)
                float es[16];
#pragma unroll
                for (int j = 0; j < 16; j++) es[j] = expf(v[j]);
#pragma unroll
                for (int off = 4; off < 32; off <<= 1)
#pragma unroll
                    for (int j = 0; j < 16; j++)
                        es[j] += __shfl_xor_sync(0xffffffffu, es[j], off);
                if (quad == 0) {
#pragma unroll
                    for (int j = 0; j < 16; j++)
                        atomicAdd(&scr[wn + (j >> 1) * 8 + qt * 2 + (j & 1)], es[j]);
                }
            }
            int row = bm + wm + mb * 16 + h * 8 + quad;
            float* crow = C + (size_t)row * DIM + cbn + wn + qt * 2;
#pragma unroll
            for (int nb = 0; nb < 8; nb++)
                *(float2*)&crow[nb * 8] = make_float2(v[nb * 2], v[nb * 2 + 1]);
        }
    }
    if (isq) {
        __syncthreads();
        if (tid < 128) {
            int b = blockIdx.y >> 5;   // 32 m-tiles per batch
            atomicAdd(&g_qsum[b * DIM + bn + tid], scr[tid]);
        }
    }
}

// ---------------- attention middle --------------------------------------------
__global__ __launch_bounds__(256)
void ctx_partial()
{
    int bh = blockIdx.y;
    int n0 = blockIdx.x * 128;
    const size_t rowbase = ((size_t)(bh >> 4) * SEQ + n0);
    const float* qb = g_q + rowbase * DIM + (bh & 15) * DHEAD;
    const float* vb = g_v + rowbase * DIM + (bh & 15) * DHEAD;

    __shared__ float ks[16][64];
    __shared__ float vs[16][64];
    __shared__ float sci[64];
    int tid = threadIdx.x;
    if (tid < 64) sci[tid] = g_cinv[bh * 64 + tid];

    const int lr = tid >> 4, lc = (tid & 15) * 4;
    const int td = (tid >> 4) * 4, te = (tid & 15) * 4;
    float acc[4][4];
#pragma unroll
    for (int i = 0; i < 4; i++)
#pragma unroll
        for (int j = 0; j < 4; j++) acc[i][j] = 0.f;
    __syncthreads();

    for (int nt = 0; nt < 128; nt += 16) {
        float4 qv = *(const float4*)&qb[(size_t)(nt + lr) * DIM + lc];
        ks[lr][lc + 0] = expf(qv.x) * sci[lc + 0];
        ks[lr][lc + 1] = expf(qv.y) * sci[lc + 1];
        ks[lr][lc + 2] = expf(qv.z) * sci[lc + 2];
        ks[lr][lc + 3] = expf(qv.w) * sci[lc + 3];
        *(float4*)&vs[lr][lc] = *(const float4*)&vb[(size_t)(nt + lr) * DIM + lc];
        __syncthreads();
#pragma unroll
        for (int nn = 0; nn < 16; nn++) {
            float kr[4] = {ks[nn][td], ks[nn][td + 1], ks[nn][td + 2], ks[nn][td + 3]};
            float4 vv = *(const float4*)&vs[nn][te];
            float vr[4] = {vv.x, vv.y, vv.z, vv.w};
#pragma unroll
            for (int i = 0; i < 4; i++)
#pragma unroll
                for (int j = 0; j < 4; j++) acc[i][j] += kr[i] * vr[j];
        }
        __syncthreads();
    }

    float* cb = g_ctx + (size_t)bh * 64 * 64;
#pragma unroll
    for (int i = 0; i < 4; i++)
#pragma unroll
        for (int j = 0; j < 4; j++)
            atomicAdd(&cb[(td + i) * 64 + te + j], acc[i][j]);
}

// attn[n,e] = sum_d q[n,d]*ctx[d,e] -> emit bf16 hi/lo directly for O-proj
__global__ __launch_bounds__(256)
void attn_apply(__nv_bfloat16* __restrict__ ahi, __nv_bfloat16* __restrict__ alo)
{
    int bh = blockIdx.y;
    int n0 = blockIdx.x * 128;
    __shared__ float cs[64][64];
    int tid = threadIdx.x;
    const float* cb = g_ctx + (size_t)bh * 4096;
#pragma unroll
    for (int i = 0; i < 4; i++) {
        int idx = i * 1024 + tid * 4;
        *(float4*)&((float*)cs)[idx] = *(const float4*)&cb[idx];
    }
    const size_t rowbase = ((size_t)(bh >> 4) * SEQ + n0);
    const float* qb = g_q + rowbase * DIM + (bh & 15) * DHEAD;
    __nv_bfloat16* oh = ahi + rowbase * DIM + (bh & 15) * DHEAD;
    __nv_bfloat16* ol = alo + rowbase * DIM + (bh & 15) * DHEAD;

    const int r0 = (tid >> 3) * 4;
    const int e0 = (tid & 7) * 8;
    float acc[4][8];
#pragma unroll
    for (int i = 0; i < 4; i++)
#pragma unroll
        for (int j = 0; j < 8; j++) acc[i][j] = 0.f;
    __syncthreads();

    for (int d4 = 0; d4 < 64; d4 += 4) {
        float4 a[4];
#pragma unroll
        for (int i = 0; i < 4; i++)
            a[i] = *(const float4*)&qb[(size_t)(r0 + i) * DIM + d4];
#pragma unroll
        for (int dd = 0; dd < 4; dd++) {
            float4 b0 = *(const float4*)&cs[d4 + dd][e0];
            float4 b1 = *(const float4*)&cs[d4 + dd][e0 + 4];
#pragma unroll
            for (int i = 0; i < 4; i++) {
                float aa = ((const float*)&a[i])[dd];
                acc[i][0] += aa * b0.x; acc[i][1] += aa * b0.y;
                acc[i][2] += aa * b0.z; acc[i][3] += aa * b0.w;
                acc[i][4] += aa * b1.x; acc[i][5] += aa * b1.y;
                acc[i][6] += aa * b1.z; acc[i][7] += aa * b1.w;
            }
        }
    }
#pragma unroll
    for (int i = 0; i < 4; i++) {
        uint32_t ph[4], pl[4];
#pragma unroll
        for (int j = 0; j < 4; j++) {
            float v0 = acc[i][j * 2], v1 = acc[i][j * 2 + 1];
            __nv_bfloat16 h0 = __float2bfloat16(v0), h1 = __float2bfloat16(v1);
            __nv_bfloat16 l0 = __float2bfloat16(v0 - __bfloat162float(h0));
            __nv_bfloat16 l1 = __float2bfloat16(v1 - __bfloat162float(h1));
            ph[j] = (uint32_t)__bfloat16_as_ushort(h0) |
                    ((uint32_t)__bfloat16_as_ushort(h1) << 16);
            pl[j] = (uint32_t)__bfloat16_as_ushort(l0) |
                    ((uint32_t)__bfloat16_as_ushort(l1) << 16);
        }
        size_t off = (size_t)(r0 + i) * DIM + e0;
        *(uint4*)&oh[off] = make_uint4(ph[0], ph[1], ph[2], ph[3]);
        *(uint4*)&ol[off] = make_uint4(pl[0], pl[1], pl[2], pl[3]);
    }
}

// -----------------------------------------------------------------------------
extern "C" void kernel_launch(void* const* d_in, const int* in_sizes, int n_in,
                              void* d_out, int out_size)
{
    const float* x  = (const float*)d_in[0];
    const float* Wq = (const float*)d_in[1];
    const float* bq = (const float*)d_in[2];
    const float* Wv = (const float*)d_in[5];
    const float* bv = (const float*)d_in[6];
    const float* Wo = (const float*)d_in[7];
    const float* bo = (const float*)d_in[8];
    float* out = (float*)d_out;

    float *qp, *vp, *bqv;
    __nv_bfloat16 *ahi, *alo, *wthi, *wtlo;
    cudaGetSymbolAddress((void**)&qp, g_q);
    cudaGetSymbolAddress((void**)&vp, g_v);
    cudaGetSymbolAddress((void**)&bqv, g_bqv);
    cudaGetSymbolAddress((void**)&ahi, g_ahi);
    cudaGetSymbolAddress((void**)&alo, g_alo);
    cudaGetSymbolAddress((void**)&wthi, g_wthi);
    cudaGetSymbolAddress((void**)&wtlo, g_wtlo);

    const int SMEM = 3 * STG_BYTES + 256;
    cudaFuncSetAttribute(gemm_mma, cudaFuncAttributeMaxDynamicSharedMemorySize, SMEM);

    const int n4 = MROWS * DIM / 4;
    dim3 tgrid(DIM / 32, DIM / 32), tblk(32, 8);

    split_bf16<<<(n4 + 255) / 256, 256>>>((const float4*)x, (uint2*)ahi, (uint2*)alo, n4);
    transpose_split<<<tgrid, tblk>>>(Wq, wthi, wtlo);
    transpose_split<<<tgrid, tblk>>>(Wv, wthi + (size_t)DIM * DIM, wtlo + (size_t)DIM * DIM);
    transpose_split<<<tgrid, tblk>>>(Wo, wthi + 2 * (size_t)DIM * DIM, wtlo + 2 * (size_t)DIM * DIM);
    setup_misc<<<(BATCH * HEADS * DHEAD * DHEAD + 255) / 256, 256>>>(bq, bv);

    // fused QV GEMM: B = [Wq^T ; Wv^T] (contiguous in g_wthi/g_wtlo), N = 2048
    gemm_mma<<<dim3(2 * DIM / 128, MROWS / 128), 256, SMEM>>>(
        ahi, alo, wthi, wtlo, bqv, qp, vp, 0);
    compute_cinv<<<(BATCH * DIM + 255) / 256, 256>>>();
    ctx_partial<<<dim3(SEQ / 128, BATCH * HEADS), 256>>>();
    attn_apply<<<dim3(SEQ / 128, BATCH * HEADS), 256>>>(ahi, alo);
    gemm_mma<<<dim3(DIM / 128, MROWS / 128), 256, SMEM>>>(
        ahi, alo, wthi + 2 * (size_t)DIM * DIM, wtlo + 2 * (size_t)DIM * DIM,
        bo, out, nullptr, 1);
}

// round 5
// speedup vs baseline: 2.8380x; 1.2805x over previous
#include <cuda_runtime.h>
#include <cuda_fp16.h>
#include <math.h>
#include <stdint.h>

#define BATCH 4
#define SEQ   4096
#define DIM   1024
#define HEADS 16
#define DHEAD 64
#define MROWS (BATCH*SEQ)                 // 16384
#define SCALE 0.5946035575013605f         // (sqrt(64))^(-0.25)

// ---------------- scratch ----------------------------------------------------
__device__ float g_q[(size_t)MROWS * DIM];       // softmaxed q (fp32, for ctx)
__device__ float g_v[(size_t)MROWS * DIM];
__device__ float g_ctx[BATCH * HEADS * DHEAD * DHEAD];
__device__ float g_cinv[BATCH * HEADS * DHEAD];
__device__ float g_qsum[BATCH * DIM];
__device__ float g_bqv[2 * DIM];
__device__ __half g_xh[(size_t)MROWS * DIM];     // x as fp16 (A of QV gemm)
__device__ __half g_qh[(size_t)MROWS * DIM];     // q as fp16 (A of O gemm)
__device__ __half g_wth[2u * DIM * DIM];         // [Wq^T;Wv^T] hi fp16
__device__ __half g_wtl[2u * DIM * DIM];         // lo fp16
__device__ __half g_foldh[(size_t)BATCH * DIM * DIM];  // Wfold^T hi per batch
__device__ __half g_foldl[(size_t)BATCH * DIM * DIM];

// ---------------- helpers ----------------------------------------------------
__device__ __forceinline__ uint32_t smem_u32(const void* p) {
    uint32_t a;
    asm("{ .reg .u64 t; cvta.to.shared.u64 t, %1; cvt.u32.u64 %0, t; }"
        : "=r"(a) : "l"(p));
    return a;
}
__device__ __forceinline__ void cp16(uint32_t dst, const void* src) {
    asm volatile("cp.async.cg.shared.global [%0], [%1], 16;" :: "r"(dst), "l"(src));
}
#define SWZ(x) ((x) ^ (((x) >> 3) & 0x70))

__device__ __forceinline__ void ldsm4(uint32_t addr, uint32_t& r0, uint32_t& r1,
                                      uint32_t& r2, uint32_t& r3) {
    asm volatile("ldmatrix.sync.aligned.m8n8.x4.shared.b16 {%0,%1,%2,%3}, [%4];"
                 : "=r"(r0), "=r"(r1), "=r"(r2), "=r"(r3) : "r"(addr));
}
__device__ __forceinline__ void mma16816(float* d, const uint32_t* a,
                                         const uint32_t* b) {
    asm volatile("mma.sync.aligned.m16n8k16.row.col.f32.f16.f16.f32 "
                 "{%0,%1,%2,%3}, {%4,%5,%6,%7}, {%8,%9}, {%0,%1,%2,%3};"
                 : "+f"(d[0]), "+f"(d[1]), "+f"(d[2]), "+f"(d[3])
                 : "r"(a[0]), "r"(a[1]), "r"(a[2]), "r"(a[3]),
                   "r"(b[0]), "r"(b[1]));
}

// ---------------- conversion / setup kernels ---------------------------------
__global__ void to_half(const float4* __restrict__ in, uint2* __restrict__ out, int n4)
{
    int i = blockIdx.x * blockDim.x + threadIdx.x;
    if (i >= n4) return;
    float4 v = in[i];
    __half2 a = __floats2half2_rn(v.x, v.y);
    __half2 b = __floats2half2_rn(v.z, v.w);
    out[i] = make_uint2(*(uint32_t*)&a, *(uint32_t*)&b);
}

// W [K,N] row-major fp32 -> Wt [N,K] fp16 hi/lo
__global__ void transpose_split(const float* __restrict__ W,
                                __half* __restrict__ th, __half* __restrict__ tl)
{
    __shared__ float t[32][33];
    int bx = blockIdx.x * 32, by = blockIdx.y * 32;
    int x = threadIdx.x, y0 = threadIdx.y;
#pragma unroll
    for (int j = 0; j < 32; j += 8)
        t[y0 + j][x] = W[(size_t)(by + y0 + j) * DIM + bx + x];
    __syncthreads();
#pragma unroll
    for (int j = 0; j < 32; j += 8) {
        float v = t[x][y0 + j];
        __half h = __float2half_rn(v);
        __half l = __float2half_rn(v - __half2float(h));
        size_t o = (size_t)(bx + y0 + j) * DIM + by + x;
        th[o] = h;
        tl[o] = l;
    }
}

__global__ void setup_misc(const float* __restrict__ bq, const float* __restrict__ bv)
{
    int i = blockIdx.x * blockDim.x + threadIdx.x;
    if (i < DIM) g_bqv[i] = bq[i];
    else if (i < 2 * DIM) g_bqv[i] = bv[i - DIM];
    if (i < BATCH * DIM) g_qsum[i] = 0.f;
    if (i < BATCH * HEADS * DHEAD * DHEAD) g_ctx[i] = 0.f;
}

__global__ void compute_cinv()
{
    int i = blockIdx.x * blockDim.x + threadIdx.x;
    if (i < BATCH * DIM) g_cinv[i] = SCALE / g_qsum[i];
}

// ---------------- fp16 2-pass mma.sync GEMM ----------------------------------
// C = A(fp16) @ (Bhi + Blo)^T + bias.  CTA 128x128, K-tile 64, 4-stage pipe.
// mode 0: fused QV (softmax+qsum+qh for bn<1024 -> Cq; else -> Cv)
// mode 1: O-proj, B per batch (blockIdx.y>>5)
#define NITER 16
#define STG_BYTES 49152   // 16KB A + 16KB Bhi + 16KB Blo

__global__ __launch_bounds__(256, 1)
void gemm_mma(const __half* __restrict__ Ah,
              const __half* __restrict__ Bh0, const __half* __restrict__ Bl0,
              const float* __restrict__ bias, float* __restrict__ Cq,
              float* __restrict__ Cv, __half* __restrict__ Qh, int mode)
{
    extern __shared__ char smem_raw[];
    const uint32_t sb = (smem_u32(smem_raw) + 127) & ~127u;
    float* scr = (float*)smem_raw;
    const int tid = threadIdx.x, wid = tid >> 5, lane = tid & 31;
    const int bm = blockIdx.y * 128, bn = blockIdx.x * 128;
    const int wm = (wid >> 1) * 32;
    const int wn = (wid & 1) * 64;

    const __half* Bh = Bh0;
    const __half* Bl = Bl0;
    if (mode == 1) {
        size_t boff = (size_t)(blockIdx.y >> 5) * DIM * DIM;
        Bh += boff; Bl += boff;
    }
    const bool isq = (mode == 0) && (bn < 1024);
    float* C = (mode == 0 && bn >= 1024) ? Cv : Cq;
    const int cbn = (mode == 0 && bn >= 1024) ? bn - 1024 : bn;

    const int lrow = tid >> 1;
    const int lci = (tid & 1) * 4;

    auto load = [&](int it) {
        const int k0 = it << 6;
        const __half* A = Ah + (size_t)(bm + lrow) * DIM + k0 + lci * 8;
        const __half* BH = Bh + (size_t)(bn + lrow) * DIM + k0 + lci * 8;
        const __half* BL = Bl + (size_t)(bn + lrow) * DIM + k0 + lci * 8;
        const uint32_t base = sb + (uint32_t)(it & 3) * STG_BYTES;
#pragma unroll
        for (int i = 0; i < 4; i++)
            cp16(base + SWZ((uint32_t)(lrow * 128 + (lci + i) * 16)), A + i * 8);
#pragma unroll
        for (int i = 0; i < 4; i++)
            cp16(base + 16384 + SWZ((uint32_t)(lrow * 128 + (lci + i) * 16)), BH + i * 8);
#pragma unroll
        for (int i = 0; i < 4; i++)
            cp16(base + 32768 + SWZ((uint32_t)(lrow * 128 + (lci + i) * 16)), BL + i * 8);
        asm volatile("cp.async.commit_group;" ::: "memory");
    };

    float acc[2][8][4];
#pragma unroll
    for (int mb = 0; mb < 2; mb++)
#pragma unroll
        for (int nb = 0; nb < 8; nb++)
#pragma unroll
            for (int j = 0; j < 4; j++) acc[mb][nb][j] = 0.f;

    load(0); load(1); load(2);

    const int la_row = lane & 15;
    const int la_kh = lane >> 4;
    const int lb_n = ((lane >> 4) << 3) + (lane & 7);
    const int lb_kh = (lane >> 3) & 1;

    for (int it = 0; it < NITER; it++) {
        asm volatile("cp.async.wait_group 2;" ::: "memory");
        __syncthreads();
        if (it + 3 < NITER) load(it + 3);
        else asm volatile("cp.async.commit_group;" ::: "memory");  // keep group count

        const uint32_t abase = sb + (uint32_t)(it & 3) * STG_BYTES;
#pragma unroll
        for (int kk = 0; kk < 4; kk++) {
            uint32_t af[2][4];
#pragma unroll
            for (int mb = 0; mb < 2; mb++) {
                uint32_t off = (uint32_t)((wm + mb * 16 + la_row) * 128 +
                                          (kk * 16 + la_kh * 8) * 2);
                ldsm4(abase + SWZ(off), af[mb][0], af[mb][1], af[mb][2], af[mb][3]);
            }
            const uint32_t boff_n = (uint32_t)((wn + lb_n) * 128 +
                                               (kk * 16 + lb_kh * 8) * 2);
#pragma unroll
            for (int half = 0; half < 2; half++) {
                const uint32_t bbase = abase + 16384 + (uint32_t)half * 16384;
                uint32_t bf[8][2];
#pragma unroll
                for (int nb2 = 0; nb2 < 4; nb2++) {
                    uint32_t r0, r1, r2, r3;
                    ldsm4(bbase + SWZ(boff_n + (uint32_t)(nb2 * 16 * 128)),
                          r0, r1, r2, r3);
                    bf[nb2 * 2][0] = r0;     bf[nb2 * 2][1] = r1;
                    bf[nb2 * 2 + 1][0] = r2; bf[nb2 * 2 + 1][1] = r3;
                }
#pragma unroll
                for (int mb = 0; mb < 2; mb++)
#pragma unroll
                    for (int nb = 0; nb < 8; nb++)
                        mma16816(acc[mb][nb], af[mb], bf[nb]);
            }
        }
    }

    // ---- epilogue ----
    __syncthreads();
    if (tid < 128) scr[tid] = 0.f;
    __syncthreads();

    const int quad = lane >> 2, qt = lane & 3;
    float bia[8][2];
#pragma unroll
    for (int nb = 0; nb < 8; nb++) {
        int col = bn + wn + nb * 8 + qt * 2;
        bia[nb][0] = bias[col];
        bia[nb][1] = bias[col + 1];
    }
#pragma unroll
    for (int mb = 0; mb < 2; mb++) {
#pragma unroll
        for (int h = 0; h < 2; h++) {
            float v[16];
#pragma unroll
            for (int nb = 0; nb < 8; nb++) {
                v[nb * 2]     = acc[mb][nb][h * 2]     + bia[nb][0];
                v[nb * 2 + 1] = acc[mb][nb][h * 2 + 1] + bia[nb][1];
            }
            int row = bm + wm + mb * 16 + h * 8 + quad;
            if (isq) {
                float m = v[0];
#pragma unroll
                for (int j = 1; j < 16; j++) m = fmaxf(m, v[j]);
                m = fmaxf(m, __shfl_xor_sync(0xffffffffu, m, 1));
                m = fmaxf(m, __shfl_xor_sync(0xffffffffu, m, 2));
                float s = 0.f;
#pragma unroll
                for (int j = 0; j < 16; j++) { v[j] = expf(v[j] - m); s += v[j]; }
                s += __shfl_xor_sync(0xffffffffu, s, 1);
                s += __shfl_xor_sync(0xffffffffu, s, 2);
                float inv = SCALE / s;
#pragma unroll
                for (int j = 0; j < 16; j++) v[j] *= inv;
                // column sums of exp(q) (bounded: q in [0, SCALE], no max needed)
                float es[16];
#pragma unroll
                for (int j = 0; j < 16; j++) es[j] = expf(v[j]);
#pragma unroll
                for (int off = 4; off < 32; off <<= 1)
#pragma unroll
                    for (int j = 0; j < 16; j++)
                        es[j] += __shfl_xor_sync(0xffffffffu, es[j], off);
                if (quad == 0) {
#pragma unroll
                    for (int j = 0; j < 16; j++)
                        atomicAdd(&scr[wn + (j >> 1) * 8 + qt * 2 + (j & 1)], es[j]);
                }
                // q as fp16 for the O-proj GEMM
                __half* qrow = Qh + (size_t)row * DIM + cbn + wn + qt * 2;
#pragma unroll
                for (int nb = 0; nb < 8; nb++) {
                    __half2 hh = __floats2half2_rn(v[nb * 2], v[nb * 2 + 1]);
                    *(__half2*)&qrow[nb * 8] = hh;
                }
            }
            float* crow = C + (size_t)row * DIM + cbn + wn + qt * 2;
#pragma unroll
            for (int nb = 0; nb < 8; nb++)
                *(float2*)&crow[nb * 8] = make_float2(v[nb * 2], v[nb * 2 + 1]);
        }
    }
    if (isq) {
        __syncthreads();
        if (tid < 128) {
            int b = blockIdx.y >> 5;
            atomicAdd(&g_qsum[b * DIM + bn + tid], scr[tid]);
        }
    }
}

// ---------------- attention middle --------------------------------------------
__global__ __launch_bounds__(256)
void ctx_partial()
{
    int bh = blockIdx.y;
    int n0 = blockIdx.x * 128;
    const size_t rowbase = ((size_t)(bh >> 4) * SEQ + n0);
    const float* qb = g_q + rowbase * DIM + (bh & 15) * DHEAD;
    const float* vb = g_v + rowbase * DIM + (bh & 15) * DHEAD;

    __shared__ float ks[16][64];
    __shared__ float vs[16][64];
    __shared__ float sci[64];
    int tid = threadIdx.x;
    if (tid < 64) sci[tid] = g_cinv[bh * 64 + tid];

    const int lr = tid >> 4, lc = (tid & 15) * 4;
    const int td = (tid >> 4) * 4, te = (tid & 15) * 4;
    float acc[4][4];
#pragma unroll
    for (int i = 0; i < 4; i++)
#pragma unroll
        for (int j = 0; j < 4; j++) acc[i][j] = 0.f;
    __syncthreads();

    for (int nt = 0; nt < 128; nt += 16) {
        float4 qv = *(const float4*)&qb[(size_t)(nt + lr) * DIM + lc];
        ks[lr][lc + 0] = expf(qv.x) * sci[lc + 0];
        ks[lr][lc + 1] = expf(qv.y) * sci[lc + 1];
        ks[lr][lc + 2] = expf(qv.z) * sci[lc + 2];
        ks[lr][lc + 3] = expf(qv.w) * sci[lc + 3];
        *(float4*)&vs[lr][lc] = *(const float4*)&vb[(size_t)(nt + lr) * DIM + lc];
        __syncthreads();
#pragma unroll
        for (int nn = 0; nn < 16; nn++) {
            float kr[4] = {ks[nn][td], ks[nn][td + 1], ks[nn][td + 2], ks[nn][td + 3]};
            float4 vv = *(const float4*)&vs[nn][te];
            float vr[4] = {vv.x, vv.y, vv.z, vv.w};
#pragma unroll
            for (int i = 0; i < 4; i++)
#pragma unroll
                for (int j = 0; j < 4; j++) acc[i][j] += kr[i] * vr[j];
        }
        __syncthreads();
    }

    float* cb = g_ctx + (size_t)bh * 64 * 64;
#pragma unroll
    for (int i = 0; i < 4; i++)
#pragma unroll
        for (int j = 0; j < 4; j++)
            atomicAdd(&cb[(td + i) * 64 + te + j], acc[i][j]);
}

// Wfold^T[b][j][h*64+d] = sum_e ctx[b,h,d,e] * Wo[h*64+e][j]  -> fp16 hi/lo
__global__ __launch_bounds__(256)
void fold_wo(const float* __restrict__ Wo, __half* __restrict__ fh,
             __half* __restrict__ fl)
{
    int bh = blockIdx.y;               // 0..63
    int jt = blockIdx.x * 128;         // 8 j-tiles
    __shared__ float cs[64][65];
    int tid = threadIdx.x;
    const float* cb = g_ctx + (size_t)bh * 4096;
    for (int i = tid; i < 4096; i += 256) cs[i >> 6][i & 63] = cb[i];
    __syncthreads();

    int j = jt + (tid & 127);
    int dbase = (tid >> 7) * 32;
    float acc[32];
#pragma unroll
    for (int d = 0; d < 32; d++) acc[d] = 0.f;
    const float* wo = Wo + (size_t)((bh & 15) * 64) * DIM + j;
    for (int e = 0; e < 64; e++) {
        float w = wo[(size_t)e * DIM];
#pragma unroll
        for (int d = 0; d < 32; d++) acc[d] += cs[dbase + d][e] * w;
    }
    size_t base = ((size_t)(bh >> 4) * DIM + j) * DIM + (bh & 15) * 64 + dbase;
#pragma unroll
    for (int d = 0; d < 32; d++) {
        float v = acc[d];
        __half h = __float2half_rn(v);
        __half l = __float2half_rn(v - __half2float(h));
        fh[base + d] = h;
        fl[base + d] = l;
    }
}

// -----------------------------------------------------------------------------
extern "C" void kernel_launch(void* const* d_in, const int* in_sizes, int n_in,
                              void* d_out, int out_size)
{
    const float* x  = (const float*)d_in[0];
    const float* Wq = (const float*)d_in[1];
    const float* bq = (const float*)d_in[2];
    const float* Wv = (const float*)d_in[5];
    const float* bv = (const float*)d_in[6];
    const float* Wo = (const float*)d_in[7];
    const float* bo = (const float*)d_in[8];
    float* out = (float*)d_out;

    float *qp, *vp, *bqv;
    __half *xh, *qh, *wth, *wtl, *foldh, *foldl;
    cudaGetSymbolAddress((void**)&qp, g_q);
    cudaGetSymbolAddress((void**)&vp, g_v);
    cudaGetSymbolAddress((void**)&bqv, g_bqv);
    cudaGetSymbolAddress((void**)&xh, g_xh);
    cudaGetSymbolAddress((void**)&qh, g_qh);
    cudaGetSymbolAddress((void**)&wth, g_wth);
    cudaGetSymbolAddress((void**)&wtl, g_wtl);
    cudaGetSymbolAddress((void**)&foldh, g_foldh);
    cudaGetSymbolAddress((void**)&foldl, g_foldl);

    const int SMEM = 4 * STG_BYTES + 256;   // 192KB + pad
    cudaFuncSetAttribute(gemm_mma, cudaFuncAttributeMaxDynamicSharedMemorySize, SMEM);

    const int n4 = MROWS * DIM / 4;
    dim3 tgrid(DIM / 32, DIM / 32), tblk(32, 8);

    to_half<<<(n4 + 255) / 256, 256>>>((const float4*)x, (uint2*)xh, n4);
    transpose_split<<<tgrid, tblk>>>(Wq, wth, wtl);
    transpose_split<<<tgrid, tblk>>>(Wv, wth + (size_t)DIM * DIM, wtl + (size_t)DIM * DIM);
    setup_misc<<<(BATCH * HEADS * DHEAD * DHEAD + 255) / 256, 256>>>(bq, bv);

    // fused QV GEMM: N = 2048
    gemm_mma<<<dim3(2 * DIM / 128, MROWS / 128), 256, SMEM>>>(
        xh, wth, wtl, bqv, qp, vp, qh, 0);
    compute_cinv<<<(BATCH * DIM + 255) / 256, 256>>>();
    ctx_partial<<<dim3(SEQ / 128, BATCH * HEADS), 256>>>();
    fold_wo<<<dim3(DIM / 128, BATCH * HEADS), 256>>>(Wo, foldh, foldl);
    // O GEMM: out = qh @ Wfold[b]^T + bo
    gemm_mma<<<dim3(DIM / 128, MROWS / 128), 256, SMEM>>>(
        qh, foldh, foldl, bo, out, nullptr, nullptr, 1);
}